// round 12
// baseline (speedup 1.0000x reference)
#include <cuda_runtime.h>
#include <math_constants.h>

// NNLoss: bidirectional 2-D NN loss via EQUAL-MASS grid binning.
// Cell boundaries = standard-normal quantiles => ~2 points/cell uniformly.
// Query fast path = 5x5 box (~50 candidates, expansion probability ~1e-3);
// sound termination via actual boundary-gap bound.

namespace {
constexpr int   Bc   = 64;
constexpr int   Nc   = 2048;
constexpr int   NSB  = 2 * Bc;            // (set, batch) segments = 128
constexpr int   G    = 32;
constexpr int   G2   = G * G;             // 1024 cells
constexpr int   SST  = G2 + 8;            // starts stride (padded)
constexpr int   TPB  = 256;
constexpr int   QCH  = Nc / TPB;          // 8 query chunks per (dir,b)
}

// standard-normal quantiles Phi^-1(i/32), i=1..31 (monotone; exactness
// irrelevant for correctness, only load balance)
__constant__ float c_qb[G - 1] = {
    -1.8627f, -1.5341f, -1.3180f, -1.1503f, -1.0100f, -0.8871f, -0.7764f,
    -0.6745f, -0.5791f, -0.4888f, -0.4023f, -0.3186f, -0.2372f, -0.1573f,
    -0.0784f,  0.0000f,  0.0784f,  0.1573f,  0.2372f,  0.3186f,  0.4023f,
     0.4888f,  0.5791f,  0.6745f,  0.7764f,  0.8871f,  1.0100f,  1.1503f,
     1.3180f,  1.5341f,  1.8627f };

__device__ unsigned short g_start[NSB * SST];   // exclusive cell starts (+total)
__device__ float2         g_sorted[NSB * Nc];   // cell-sorted {x, y}

// branchless 5-step binary search: returns max c in [0,31] with sB[c] <= x
__device__ __forceinline__ int qcell(const float* sB, float x) {
    int c = (x >= sB[16]) ? 16 : 0;
    c += (x >= sB[c + 8]) ? 8 : 0;
    c += (x >= sB[c + 4]) ? 4 : 0;
    c += (x >= sB[c + 2]) ? 2 : 0;
    c += (x >= sB[c + 1]) ? 1 : 0;
    return c;
}
__device__ __forceinline__ void load_bounds(float* sB, int tid) {
    if (tid < G - 1) sB[tid + 1] = c_qb[tid];
    if (tid == G - 1) { sB[0] = -1e30f; sB[G] = 1e30f; }
}

// ---------------- Kernel 1: block-local binning ----------------
__global__ __launch_bounds__(TPB)
void bin_kernel(const float* __restrict__ preds,
                const float* __restrict__ targs,
                float* __restrict__ out)
{
    __shared__ float2 pts[Nc];             // 16KB
    __shared__ unsigned short cid[Nc];     // 4KB: cached cell ids
    __shared__ unsigned int scnt[G2];      // counts -> scatter cursors
    __shared__ unsigned int part[TPB];
    __shared__ float sB[G + 1];

    const int sb  = blockIdx.x;            // set*64 + b
    const int set = sb >> 6;
    const int b   = sb & (Bc - 1);
    if (sb == 0 && threadIdx.x == 0) out[0] = 0.0f;

    load_bounds(sB, threadIdx.x);
    const float4* src = reinterpret_cast<const float4*>(set ? targs : preds)
                      + (size_t)b * Nc;
#pragma unroll
    for (int i = 0; i < Nc / TPB; ++i) {
        float4 p = src[threadIdx.x + i * TPB];
        pts[threadIdx.x + i * TPB] = make_float2(p.x, p.y);
    }
#pragma unroll
    for (int i = 0; i < G2 / TPB; ++i)
        scnt[threadIdx.x + i * TPB] = 0u;
    __syncthreads();

#pragma unroll
    for (int i = 0; i < Nc / TPB; ++i) {
        int t = threadIdx.x + i * TPB;
        float2 p = pts[t];
        int c = qcell(sB, p.y) * G + qcell(sB, p.x);
        cid[t] = (unsigned short)c;
        atomicAdd(&scnt[c], 1u);
    }
    __syncthreads();

    // block exclusive scan of 1024 counters (4 per thread)
    unsigned int v[4], sum = 0;
    const int base = threadIdx.x * 4;
#pragma unroll
    for (int i = 0; i < 4; ++i) { v[i] = scnt[base + i]; sum += v[i]; }
    part[threadIdx.x] = sum;
    __syncthreads();
    for (int off = 1; off < TPB; off <<= 1) {
        unsigned int a = (threadIdx.x >= off) ? part[threadIdx.x - off] : 0u;
        __syncthreads();
        if (threadIdx.x >= off) part[threadIdx.x] += a;
        __syncthreads();
    }
    unsigned int run = threadIdx.x ? part[threadIdx.x - 1] : 0u;
    unsigned short* st = g_start + sb * SST;
#pragma unroll
    for (int i = 0; i < 4; ++i) {
        scnt[base + i] = run;                       // scatter cursor
        st[base + i]   = (unsigned short)run;
        run += v[i];
    }
    if (threadIdx.x == TPB - 1) st[G2] = (unsigned short)run;   // 2048
    __syncthreads();

    float2* dst = g_sorted + (size_t)sb * Nc;
#pragma unroll
    for (int i = 0; i < Nc / TPB; ++i) {
        int t = threadIdx.x + i * TPB;
        unsigned int pos = atomicAdd(&scnt[cid[t]], 1u);
        dst[pos] = pts[t];
    }
}

// ---------------- Kernel 2: 5x5 box scan + gap-bounded expansion ----------------
__global__ __launch_bounds__(TPB)
void query_kernel(const float* __restrict__ subcoef, float* __restrict__ out)
{
    __shared__ float2 tile[Nc];                  // db points (cell-sorted)
    __shared__ unsigned short sst[G2 + 2];       // db cell starts
    __shared__ float sB[G + 1];
    __shared__ float red[TPB / 32];

    int bid = blockIdx.x;
    const int chunk = bid & (QCH - 1);  bid >>= 3;
    const int b     = bid & (Bc - 1);   bid >>= 6;
    const int dir   = bid;                       // 0: preds->targs, 1: targs->preds
    const int qsb = dir * Bc + b;                // query set (set0 = preds)
    const int dsb = (1 - dir) * Bc + b;          // db set

    load_bounds(sB, threadIdx.x);
    for (int t = threadIdx.x; t < Nc; t += TPB)  tile[t] = g_sorted[(size_t)dsb * Nc + t];
    for (int t = threadIdx.x; t <= G2; t += TPB) sst[t]  = g_start[dsb * SST + t];
    __syncthreads();

    // queries = own set's sorted points (order-invariant loss; cell-coherent lanes)
    float2 q = g_sorted[(size_t)qsb * Nc + chunk * TPB + threadIdx.x];
    const float qx = q.x, qy = q.y;
    const int cx = qcell(sB, qx), cy = qcell(sB, qy);

    float best = CUDART_INF_F;
    float bx = 0.0f, by = 0.0f;

    auto scan = [&](int j, int je) {
        for (; j + 1 < je; j += 2) {
            float2 t0 = tile[j];
            float2 t1 = tile[j + 1];
            float dx0 = t0.x - qx, dy0 = t0.y - qy;
            float dx1 = t1.x - qx, dy1 = t1.y - qy;
            float s0 = fmaf(dx0, dx0, dy0 * dy0);
            float s1 = fmaf(dx1, dx1, dy1 * dy1);
            if (s0 < best) { best = s0; bx = t0.x; by = t0.y; }
            if (s1 < best) { best = s1; bx = t1.x; by = t1.y; }
        }
        if (j < je) {
            float2 t0 = tile[j];
            float dx0 = t0.x - qx, dy0 = t0.y - qy;
            float s0 = fmaf(dx0, dx0, dy0 * dy0);
            if (s0 < best) { best = s0; bx = t0.x; by = t0.y; }
        }
    };
    // min distance to any cell OUTSIDE the scanned radius-r box (gap bound);
    // clamped sides yield ~1e30 via the sentinel boundaries
    auto gap2 = [&](int r) {
        float gl = qx - sB[max(cx - r, 0)];
        float gr = sB[min(cx + r + 1, G)] - qx;
        float gb = qy - sB[max(cy - r, 0)];
        float gt = sB[min(cy + r + 1, G)] - qy;
        float g  = fminf(fminf(gl, gr), fminf(gb, gt));
        return g * g;
    };

    // fast path: 5x5 box (~50 candidates), five contiguous row spans
    {
        const int xa = max(cx - 2, 0), xb = min(cx + 2, G - 1);
        const int ya = max(cy - 2, 0), yb = min(cy + 2, G - 1);
        for (int y = ya; y <= yb; ++y)
            scan(sst[y * G + xa], sst[y * G + xb + 1]);
    }

    // expansion (rare: P(lane) ~ 1e-3): before ring k, box radius is k-1
    if (__any_sync(0xffffffffu, best > gap2(2))) {
        if (best > gap2(2)) {
            for (int k = 3; k <= G; ++k) {
                if (best <= gap2(k - 1)) break;
                const int xa = max(cx - k, 0), xb = min(cx + k, G - 1);
                const int ya = max(cy - k, 0), yb = min(cy + k, G - 1);
                for (int y = ya; y <= yb; ++y) {
                    if (y == cy - k || y == cy + k) {
                        scan(sst[y * G + xa], sst[y * G + xb + 1]);
                    } else {
                        if (cx - k >= 0) {
                            int cc = y * G + cx - k;
                            scan(sst[cc], sst[cc + 1]);
                        }
                        if (cx + k < G) {
                            int cc = y * G + cx + k;
                            scan(sst[cc], sst[cc + 1]);
                        }
                    }
                }
            }
        }
    }

    const float cA = dir ? 1.0f : subcoef[0];
    const float cB = dir ? 1.0f : subcoef[1];
    float contrib = fabsf(qx - bx) * cA + fabsf(qy - by) * cB;

#pragma unroll
    for (int o = 16; o > 0; o >>= 1)
        contrib += __shfl_down_sync(0xffffffffu, contrib, o);
    if ((threadIdx.x & 31) == 0) red[threadIdx.x >> 5] = contrib;
    __syncthreads();
    if (threadIdx.x < 32) {
        float v = (threadIdx.x < TPB / 32) ? red[threadIdx.x] : 0.0f;
#pragma unroll
        for (int o = 4; o > 0; o >>= 1)
            v += __shfl_down_sync(0x000000ffu, v, o);
        if (threadIdx.x == 0) atomicAdd(out, v);
    }
}

extern "C" void kernel_launch(void* const* d_in, const int* in_sizes, int n_in,
                              void* d_out, int out_size)
{
    const float* preds   = (const float*)d_in[0];
    const float* targs   = (const float*)d_in[1];
    const float* subcoef = (const float*)d_in[2];
    float* out = (float*)d_out;

    bin_kernel  <<<NSB, TPB>>>(preds, targs, out);          // 128 blocks
    query_kernel<<<2 * Bc * QCH, TPB>>>(subcoef, out);      // 1024 blocks
}

// round 13
// speedup vs baseline: 1.9697x; 1.9697x over previous
#include <cuda_runtime.h>
#include <math_constants.h>

// NNLoss: bidirectional 2-D NN loss via uniform-grid spatial binning (R6
// structure) with PAIRED-POINT scanning: tile stored as float4 = 2 points,
// one LDS.128 per 2 candidates, spans rounded outward to pair boundaries
// (extra points are genuine db points -> superset min, still exact).

namespace {
constexpr int   Bc   = 64;
constexpr int   Nc   = 2048;
constexpr int   NSB  = 2 * Bc;            // (set, batch) segments = 128
constexpr int   G    = 64;
constexpr int   G2   = G * G;             // 4096 cells
constexpr int   SST  = G2 + 8;            // starts stride (padded)
constexpr float EXT  = 6.0f;
constexpr float CELL = 2.0f * EXT / G;    // 0.1875
constexpr float INVC = (float)G / (2.0f * EXT);
constexpr int   TPB  = 256;
constexpr int   QCH  = Nc / TPB;          // 8 query chunks per (dir,b)
}

__device__ unsigned short g_start[NSB * SST];      // exclusive cell starts (+total)
__device__ float4         g_sorted4[NSB * Nc / 2]; // cell-sorted point PAIRS

__device__ __forceinline__ int cell_of(float v) {
    int c = __float2int_rd((v + EXT) * INVC);
    return min(G - 1, max(0, c));
}

// ---------------- Kernel 1: block-local binning ----------------
__global__ __launch_bounds__(TPB)
void bin_kernel(const float* __restrict__ preds,
                const float* __restrict__ targs,
                float* __restrict__ out)
{
    __shared__ unsigned int scnt[G2];      // counts -> scatter cursors
    __shared__ float2 pts[Nc];
    __shared__ unsigned int part[TPB];

    const int sb  = blockIdx.x;            // set*64 + b
    const int set = sb >> 6;
    const int b   = sb & (Bc - 1);
    if (sb == 0 && threadIdx.x == 0) out[0] = 0.0f;

    const float4* src = reinterpret_cast<const float4*>(set ? targs : preds)
                      + (size_t)b * Nc;
#pragma unroll
    for (int i = 0; i < Nc / TPB; ++i) {
        float4 p = src[threadIdx.x + i * TPB];
        pts[threadIdx.x + i * TPB] = make_float2(p.x, p.y);
    }
#pragma unroll
    for (int i = 0; i < G2 / TPB; ++i)
        scnt[threadIdx.x + i * TPB] = 0u;
    __syncthreads();

#pragma unroll
    for (int i = 0; i < Nc / TPB; ++i) {
        float2 p = pts[threadIdx.x + i * TPB];
        atomicAdd(&scnt[cell_of(p.y) * G + cell_of(p.x)], 1u);
    }
    __syncthreads();

    // block exclusive scan of 4096 counters
    unsigned int v[16], sum = 0;
    const int base = threadIdx.x * 16;
#pragma unroll
    for (int i = 0; i < 16; ++i) { v[i] = scnt[base + i]; sum += v[i]; }
    part[threadIdx.x] = sum;
    __syncthreads();
    for (int off = 1; off < TPB; off <<= 1) {
        unsigned int a = (threadIdx.x >= off) ? part[threadIdx.x - off] : 0u;
        __syncthreads();
        if (threadIdx.x >= off) part[threadIdx.x] += a;
        __syncthreads();
    }
    unsigned int run = threadIdx.x ? part[threadIdx.x - 1] : 0u;
    unsigned short* st = g_start + sb * SST;
#pragma unroll
    for (int i = 0; i < 16; ++i) {
        scnt[base + i] = run;                       // scatter cursor
        st[base + i]   = (unsigned short)run;
        run += v[i];
    }
    if (threadIdx.x == TPB - 1) st[G2] = (unsigned short)run;   // 2048
    __syncthreads();

    float2* dst = reinterpret_cast<float2*>(g_sorted4) + (size_t)sb * Nc;
#pragma unroll
    for (int i = 0; i < Nc / TPB; ++i) {
        float2 p = pts[threadIdx.x + i * TPB];
        unsigned int pos = atomicAdd(&scnt[cell_of(p.y) * G + cell_of(p.x)], 1u);
        dst[pos] = p;
    }
}

// ---------------- Kernel 2: paired 3x3-box scan + ring expansion ----------------
__global__ __launch_bounds__(TPB)
void query_kernel(const float* __restrict__ subcoef, float* __restrict__ out)
{
    __shared__ float4 tile4[Nc / 2];             // db point pairs (cell-sorted)
    __shared__ unsigned short sst[G2 + 1];       // db cell starts (point indices)
    __shared__ float red[TPB / 32];

    int bid = blockIdx.x;
    const int chunk = bid & (QCH - 1);  bid >>= 3;
    const int b     = bid & (Bc - 1);   bid >>= 6;
    const int dir   = bid;                       // 0: preds->targs, 1: targs->preds
    const int qsb = dir * Bc + b;                // query set (set0 = preds)
    const int dsb = (1 - dir) * Bc + b;          // db set

    {
        const float4* srcp = g_sorted4 + (size_t)dsb * (Nc / 2);
        for (int t = threadIdx.x; t < Nc / 2; t += TPB) tile4[t] = srcp[t];
        for (int t = threadIdx.x; t <= G2; t += TPB)    sst[t]  = g_start[dsb * SST + t];
    }
    __syncthreads();

    // queries = own set's sorted points (order-invariant loss; cell-coherent lanes)
    float2 q = reinterpret_cast<const float2*>(g_sorted4)
                   [(size_t)qsb * Nc + chunk * TPB + threadIdx.x];
    const float qx = q.x, qy = q.y;
    const int cx = cell_of(qx), cy = cell_of(qy);

    float best = CUDART_INF_F;                   // true squared distance
    float bx = 0.0f, by = 0.0f;

    // paired span scan: point range [j, je) rounded OUTWARD to pair bounds.
    // Extra boundary points are genuine db points -> min over superset, exact.
    auto scan = [&](int j, int je) {
        int p  = j >> 1;
        int pe = (je + 1) >> 1;
#pragma unroll 2
        for (; p < pe; ++p) {
            float4 t = tile4[p];
            float dx0 = t.x - qx, dy0 = t.y - qy;
            float dx1 = t.z - qx, dy1 = t.w - qy;
            float s0 = fmaf(dx0, dx0, dy0 * dy0);
            float s1 = fmaf(dx1, dx1, dy1 * dy1);
            if (s0 < best) { best = s0; bx = t.x; by = t.y; }
            if (s1 < best) { best = s1; bx = t.z; by = t.w; }
        }
    };

    // fast path: unconditional 3x3 box, three contiguous row spans
    {
        const int xa = max(cx - 1, 0), xb = min(cx + 1, G - 1);
        const int ya = max(cy - 1, 0), yb = min(cy + 1, G - 1);
        for (int y = ya; y <= yb; ++y)
            scan(sst[y * G + xa], sst[y * G + xb + 1]);
    }

    // exit bound: any point outside the 3x3 box is >= CELL away
    if (__any_sync(0xffffffffu, best > CELL * CELL)) {
        if (best > CELL * CELL) {
            // per-lane ring expansion; unscanned cells (Chebyshev >= k)
            // hold points at distance >= (k-1)*CELL
            for (int k = 2; k < G; ++k) {
                float bd = (float)(k - 1) * CELL;
                if (best <= bd * bd) break;
                const int xa = max(cx - k, 0), xb = min(cx + k, G - 1);
                const int ya = max(cy - k, 0), yb = min(cy + k, G - 1);
                for (int y = ya; y <= yb; ++y) {
                    if (y == cy - k || y == cy + k) {
                        scan(sst[y * G + xa], sst[y * G + xb + 1]);
                    } else {
                        if (cx - k >= 0) {
                            int cc = y * G + cx - k;
                            scan(sst[cc], sst[cc + 1]);
                        }
                        if (cx + k < G) {
                            int cc = y * G + cx + k;
                            scan(sst[cc], sst[cc + 1]);
                        }
                    }
                }
            }
        }
    }

    const float cA = dir ? 1.0f : subcoef[0];
    const float cB = dir ? 1.0f : subcoef[1];
    float contrib = fabsf(qx - bx) * cA + fabsf(qy - by) * cB;

#pragma unroll
    for (int o = 16; o > 0; o >>= 1)
        contrib += __shfl_down_sync(0xffffffffu, contrib, o);
    if ((threadIdx.x & 31) == 0) red[threadIdx.x >> 5] = contrib;
    __syncthreads();
    if (threadIdx.x < 32) {
        float v = (threadIdx.x < TPB / 32) ? red[threadIdx.x] : 0.0f;
#pragma unroll
        for (int o = 4; o > 0; o >>= 1)
            v += __shfl_down_sync(0x000000ffu, v, o);
        if (threadIdx.x == 0) atomicAdd(out, v);
    }
}

extern "C" void kernel_launch(void* const* d_in, const int* in_sizes, int n_in,
                              void* d_out, int out_size)
{
    const float* preds   = (const float*)d_in[0];
    const float* targs   = (const float*)d_in[1];
    const float* subcoef = (const float*)d_in[2];
    float* out = (float*)d_out;

    bin_kernel  <<<NSB, TPB>>>(preds, targs, out);          // 128 blocks
    query_kernel<<<2 * Bc * QCH, TPB>>>(subcoef, out);      // 1024 blocks
}

// round 14
// speedup vs baseline: 1.9876x; 1.0091x over previous
#include <cuda_runtime.h>
#include <math_constants.h>

// NNLoss: bidirectional 2-D NN loss via uniform-grid spatial binning.
// Kernel 1: per-(set,batch) block-local bin (count+scan+scatter in shared).
// Kernel 2: paired-point scan, STAGED boxes: 3x3 -> 9x9 -> rare ring loop.

namespace {
constexpr int   Bc   = 64;
constexpr int   Nc   = 2048;
constexpr int   NSB  = 2 * Bc;            // (set, batch) segments = 128
constexpr int   G    = 64;
constexpr int   G2   = G * G;             // 4096 cells
constexpr int   SST  = G2 + 8;            // starts stride (padded)
constexpr float EXT  = 6.0f;
constexpr float CELL = 2.0f * EXT / G;    // 0.1875
constexpr float INVC = (float)G / (2.0f * EXT);
constexpr int   TPB  = 256;
constexpr int   QCH  = Nc / TPB;          // 8 query chunks per (dir,b)
}

__device__ unsigned short g_start[NSB * SST];      // exclusive cell starts (+total)
__device__ float4         g_sorted4[NSB * Nc / 2]; // cell-sorted point PAIRS

__device__ __forceinline__ int cell_of(float v) {
    int c = __float2int_rd((v + EXT) * INVC);
    return min(G - 1, max(0, c));
}

// ---------------- Kernel 1: block-local binning ----------------
__global__ __launch_bounds__(TPB)
void bin_kernel(const float* __restrict__ preds,
                const float* __restrict__ targs,
                float* __restrict__ out)
{
    __shared__ unsigned int scnt[G2];      // counts -> scatter cursors
    __shared__ float2 pts[Nc];
    __shared__ unsigned int part[TPB];

    const int sb  = blockIdx.x;            // set*64 + b
    const int set = sb >> 6;
    const int b   = sb & (Bc - 1);
    if (sb == 0 && threadIdx.x == 0) out[0] = 0.0f;

    const float4* src = reinterpret_cast<const float4*>(set ? targs : preds)
                      + (size_t)b * Nc;
#pragma unroll
    for (int i = 0; i < Nc / TPB; ++i) {
        float4 p = src[threadIdx.x + i * TPB];
        pts[threadIdx.x + i * TPB] = make_float2(p.x, p.y);
    }
#pragma unroll
    for (int i = 0; i < G2 / TPB; ++i)
        scnt[threadIdx.x + i * TPB] = 0u;
    __syncthreads();

#pragma unroll
    for (int i = 0; i < Nc / TPB; ++i) {
        float2 p = pts[threadIdx.x + i * TPB];
        atomicAdd(&scnt[cell_of(p.y) * G + cell_of(p.x)], 1u);
    }
    __syncthreads();

    // block exclusive scan of 4096 counters
    unsigned int v[16], sum = 0;
    const int base = threadIdx.x * 16;
#pragma unroll
    for (int i = 0; i < 16; ++i) { v[i] = scnt[base + i]; sum += v[i]; }
    part[threadIdx.x] = sum;
    __syncthreads();
    for (int off = 1; off < TPB; off <<= 1) {
        unsigned int a = (threadIdx.x >= off) ? part[threadIdx.x - off] : 0u;
        __syncthreads();
        if (threadIdx.x >= off) part[threadIdx.x] += a;
        __syncthreads();
    }
    unsigned int run = threadIdx.x ? part[threadIdx.x - 1] : 0u;
    unsigned short* st = g_start + sb * SST;
#pragma unroll
    for (int i = 0; i < 16; ++i) {
        scnt[base + i] = run;                       // scatter cursor
        st[base + i]   = (unsigned short)run;
        run += v[i];
    }
    if (threadIdx.x == TPB - 1) st[G2] = (unsigned short)run;   // 2048
    __syncthreads();

    float2* dst = reinterpret_cast<float2*>(g_sorted4) + (size_t)sb * Nc;
#pragma unroll
    for (int i = 0; i < Nc / TPB; ++i) {
        float2 p = pts[threadIdx.x + i * TPB];
        unsigned int pos = atomicAdd(&scnt[cell_of(p.y) * G + cell_of(p.x)], 1u);
        dst[pos] = p;
    }
}

// ---------------- Kernel 2: staged-box query ----------------
__global__ __launch_bounds__(TPB)
void query_kernel(const float* __restrict__ subcoef, float* __restrict__ out)
{
    __shared__ float4 tile4[Nc / 2];             // db point pairs (cell-sorted)
    __shared__ unsigned short sst[G2 + 1];       // db cell starts (point indices)
    __shared__ float red[TPB / 32];

    int bid = blockIdx.x;
    const int chunk = bid & (QCH - 1);  bid >>= 3;
    const int b     = bid & (Bc - 1);   bid >>= 6;
    const int dir   = bid;                       // 0: preds->targs, 1: targs->preds
    const int qsb = dir * Bc + b;                // query set (set0 = preds)
    const int dsb = (1 - dir) * Bc + b;          // db set

    {
        const float4* srcp = g_sorted4 + (size_t)dsb * (Nc / 2);
        for (int t = threadIdx.x; t < Nc / 2; t += TPB) tile4[t] = srcp[t];
        for (int t = threadIdx.x; t <= G2; t += TPB)    sst[t]  = g_start[dsb * SST + t];
    }
    __syncthreads();

    // queries = own set's sorted points (order-invariant loss; cell-coherent lanes)
    float2 q = reinterpret_cast<const float2*>(g_sorted4)
                   [(size_t)qsb * Nc + chunk * TPB + threadIdx.x];
    const float qx = q.x, qy = q.y;
    const int cx = cell_of(qx), cy = cell_of(qy);

    float best = CUDART_INF_F;                   // true squared distance
    float bx = 0.0f, by = 0.0f;

    // paired span scan: point range [j, je) rounded OUTWARD to pair bounds.
    // Extra boundary points are genuine db points -> min over superset, exact.
    auto scan = [&](int j, int je) {
        int p  = j >> 1;
        int pe = (je + 1) >> 1;
#pragma unroll 2
        for (; p < pe; ++p) {
            float4 t = tile4[p];
            float dx0 = t.x - qx, dy0 = t.y - qy;
            float dx1 = t.z - qx, dy1 = t.w - qy;
            float s0 = fmaf(dx0, dx0, dy0 * dy0);
            float s1 = fmaf(dx1, dx1, dy1 * dy1);
            if (s0 < best) { best = s0; bx = t.x; by = t.y; }
            if (s1 < best) { best = s1; bx = t.z; by = t.w; }
        }
    };
    // scan box of radius r (rows as contiguous spans)
    auto box = [&](int r) {
        const int xa = max(cx - r, 0), xb = min(cx + r, G - 1);
        const int ya = max(cy - r, 0), yb = min(cy + r, G - 1);
        for (int y = ya; y <= yb; ++y)
            scan(sst[y * G + xa], sst[y * G + xb + 1]);
    };

    // stage 1: 3x3 box. Unscanned cells are Chebyshev >= 2 -> d >= CELL.
    box(1);

    if (__any_sync(0xffffffffu, best > CELL * CELL)) {
        if (best > CELL * CELL) {
            // stage 2: full 9x9 box (uniform structure; middle rescan is
            // cheap slack on a ~3% path). Unscanned -> Chebyshev >= 5
            // -> d >= 4*CELL.
            box(4);
            float b4 = 4.0f * CELL;
            if (best > b4 * b4) {
                // stage 3 (deep tail, ~0.05%): ring expansion from k=5
                for (int k = 5; k < G; ++k) {
                    float bd = (float)(k - 1) * CELL;
                    if (best <= bd * bd) break;
                    const int xa = max(cx - k, 0), xb = min(cx + k, G - 1);
                    const int ya = max(cy - k, 0), yb = min(cy + k, G - 1);
                    for (int y = ya; y <= yb; ++y) {
                        if (y == cy - k || y == cy + k) {
                            scan(sst[y * G + xa], sst[y * G + xb + 1]);
                        } else {
                            if (cx - k >= 0) {
                                int cc = y * G + cx - k;
                                scan(sst[cc], sst[cc + 1]);
                            }
                            if (cx + k < G) {
                                int cc = y * G + cx + k;
                                scan(sst[cc], sst[cc + 1]);
                            }
                        }
                    }
                }
            }
        }
    }

    const float cA = dir ? 1.0f : subcoef[0];
    const float cB = dir ? 1.0f : subcoef[1];
    float contrib = fabsf(qx - bx) * cA + fabsf(qy - by) * cB;

#pragma unroll
    for (int o = 16; o > 0; o >>= 1)
        contrib += __shfl_down_sync(0xffffffffu, contrib, o);
    if ((threadIdx.x & 31) == 0) red[threadIdx.x >> 5] = contrib;
    __syncthreads();
    if (threadIdx.x < 32) {
        float v = (threadIdx.x < TPB / 32) ? red[threadIdx.x] : 0.0f;
#pragma unroll
        for (int o = 4; o > 0; o >>= 1)
            v += __shfl_down_sync(0x000000ffu, v, o);
        if (threadIdx.x == 0) atomicAdd(out, v);
    }
}

extern "C" void kernel_launch(void* const* d_in, const int* in_sizes, int n_in,
                              void* d_out, int out_size)
{
    const float* preds   = (const float*)d_in[0];
    const float* targs   = (const float*)d_in[1];
    const float* subcoef = (const float*)d_in[2];
    float* out = (float*)d_out;

    bin_kernel  <<<NSB, TPB>>>(preds, targs, out);          // 128 blocks
    query_kernel<<<2 * Bc * QCH, TPB>>>(subcoef, out);      // 1024 blocks
}